// round 15
// baseline (speedup 1.0000x reference)
#include <cuda_runtime.h>
#include <cuda_fp16.h>
#include <cooperative_groups.h>
#include <math.h>

namespace cg = cooperative_groups;

#define BATCH   64
#define T_IN    104
#define NFEAT   20
#define NPEMB   64
#define NCOND   256
#define NSUB    40
#define NSTEPS  400
#define NBF     100

#define RANKS   4
#define BPC     2
#define RCOLS   64

// ---------------- device scratch ----------------
static __device__ float g_t   [BATCH * T_IN * NCOND];
static __device__ float g_cond[BATCH * NBF  * NCOND];
static __device__ float g_pre [BATCH * NSTEPS * NSUB];
static __device__ float g_pim [BATCH * NSTEPS * NSUB];
static __device__ float g_w1t [NCOND * 3 * NCOND];
static __device__ float g_w2t [NCOND * 3 * NCOND];
static __device__ __half g_sd1h[376 * NCOND];
static __device__ __half g_sd2h[NCOND * NCOND];
static __device__ __half g_gw[6][NCOND * 768];  // g1wi,g1wh,g2wi,g2wh,g3wi,g3wh

__device__ __forceinline__ float sigm(float x) { return 1.0f / (1.0f + expf(-x)); }

// ---------------- prep: fp16 weights + conv transpose + phase embedding ----------------
__global__ void prep_kernel(const int* __restrict__ period, const float* __restrict__ rshift,
                            const float* __restrict__ sd1, const float* __restrict__ sd2,
                            const float* __restrict__ a0, const float* __restrict__ a1,
                            const float* __restrict__ a2, const float* __restrict__ a3,
                            const float* __restrict__ a4, const float* __restrict__ a5,
                            const float* __restrict__ c1w, const float* __restrict__ c2w) {
    if (blockIdx.x < 64) {                      // phase embedding, b = blockIdx.x
        const float TWOPI = 6.28318530717958647692f;
        int b = blockIdx.x;
        __shared__ float s_cum[NBF], s_w0[NBF];
        if (threadIdx.x == 0) {
            float acc = TWOPI * rshift[b] / 160.0f;
            for (int f = 0; f < NBF; f++) {
                float w0 = TWOPI / (float)period[b * T_IN + 3 + f];
                s_w0[f] = w0; s_cum[f] = 160.0f * acc; acc += w0;
            }
        }
        __syncthreads();
        float* pre = g_pre + (size_t)b * NSTEPS * NSUB;
        float* pim = g_pim + (size_t)b * NSTEPS * NSUB;
        for (int idx = threadIdx.x; idx < NSTEPS * NSUB; idx += blockDim.x) {
            int s = idx / NSUB, j = idx - s * NSUB;
            float e = s_cum[s >> 2] + s_w0[s >> 2] * (float)((s & 3) * NSUB + j);
            double sv, cv; sincos((double)e, &sv, &cv);
            pre[idx] = (float)cv; pim[idx] = (float)sv;
        }
        return;
    }
    int i = (blockIdx.x - 64) * 256 + threadIdx.x;   // elementwise weight prep
    if (i < 376 * NCOND)   g_sd1h[i] = __float2half_rn(sd1[i]);
    if (i < NCOND * NCOND) g_sd2h[i] = __float2half_rn(sd2[i]);
    if (i < NCOND * 768) {
        g_gw[0][i] = __float2half_rn(a0[i]); g_gw[1][i] = __float2half_rn(a1[i]);
        g_gw[2][i] = __float2half_rn(a2[i]); g_gw[3][i] = __float2half_rn(a3[i]);
        g_gw[4][i] = __float2half_rn(a4[i]); g_gw[5][i] = __float2half_rn(a5[i]);
    }
    if (i < NCOND * NCOND * 3) {
        int o = i / (NCOND * 3), r = i - o * (NCOND * 3);
        g_w1t[r * NCOND + o] = c1w[i];
        g_w2t[r * NCOND + o] = c2w[i];
    }
}

// ---------------- fd1 ----------------
__global__ void fd1_kernel(const float* __restrict__ feat, const int* __restrict__ period,
                           const float* __restrict__ pemb, const float* __restrict__ w,
                           const float* __restrict__ bias) {
    int bt = blockIdx.x, tid = threadIdx.x;
    __shared__ float xs[NFEAT + NPEMB];
    if (tid < NFEAT)              xs[tid] = feat[(size_t)bt * NFEAT + tid];
    else if (tid < NFEAT + NPEMB) xs[tid] = pemb[(size_t)period[bt] * NPEMB + (tid - NFEAT)];
    __syncthreads();
    float acc = bias[tid];
#pragma unroll 4
    for (int k = 0; k < NFEAT + NPEMB; k++)
        acc = fmaf(xs[k], w[(size_t)k * NCOND + tid], acc);
    g_t[(size_t)bt * NCOND + tid] = tanhf(acc);
}

// ---------------- cond2: fused conv1+conv2+fd2, one block per (b, f) ----------------
__global__ void cond2_kernel(const float* __restrict__ c1b, const float* __restrict__ c2b,
                             const float* __restrict__ fd2w, const float* __restrict__ fd2b) {
    int bf = blockIdx.x;                 // b*100 + f
    int b = bf / NBF, f = bf - b * NBF;
    int tid = threadIdx.x;
    __shared__ float xs[5][NCOND], c1s[3][NCOND], c2s[NCOND];
#pragma unroll
    for (int d = 0; d < 5; d++)
        xs[d][tid] = g_t[((size_t)(b * T_IN + f + d)) * NCOND + tid];
    __syncthreads();
    float a0 = c1b[tid], a1 = a0, a2 = a0;
    for (int i = 0; i < NCOND; i++) {
#pragma unroll
        for (int d = 0; d < 3; d++) {
            float w = g_w1t[(size_t)(i * 3 + d) * NCOND + tid];
            a0 = fmaf(xs[d][i],     w, a0);
            a1 = fmaf(xs[d + 1][i], w, a1);
            a2 = fmaf(xs[d + 2][i], w, a2);
        }
    }
    c1s[0][tid] = tanhf(a0); c1s[1][tid] = tanhf(a1); c1s[2][tid] = tanhf(a2);
    __syncthreads();
    float acc = c2b[tid];
    for (int i = 0; i < NCOND; i++) {
#pragma unroll
        for (int d = 0; d < 3; d++)
            acc = fmaf(c1s[d][i], g_w2t[(size_t)(i * 3 + d) * NCOND + tid], acc);
    }
    c2s[tid] = tanhf(acc);
    __syncthreads();
    acc = fd2b[tid];
#pragma unroll 4
    for (int k = 0; k < NCOND; k++)
        acc = fmaf(c2s[k], fd2w[(size_t)k * NCOND + tid], acc);
    g_cond[(size_t)bf * NCOND + tid] = tanhf(acc);
}

// ======================= rnn: cluster-4, 2-batch, fp16 weights, 5 syncs/step ===========
// Rank r owns cols [64r,64r+64). P1 = sd1 + all three hidden-side gate matvecs
// (gh stays local). P2 = sd2. P3..P5 = gi_l + combine h_l (P5 adds out k-split
// partials over own h3 cols). Out finalized locally at next step start from the
// 4x80 broadcast partials. Single-buffered h (barriers order reads/writes).
struct RnnSmem {
    float4 part[768];            // 12288 B partials
    float  x2 [376 * BPC];       // [k][b]: cond|prev|pr|pi
    float  tta[NCOND * BPC];
    float  ttb[NCOND * BPC];
    float  h  [3][NCOND * BPC];
    float  ghl[3][3][RCOLS * BPC];  // [layer][gate][l64*2+b]
    float  outp[RANKS][NSUB * BPC]; // rank partials for out layer
};

__global__ void __cluster_dims__(RANKS, 1, 1) __launch_bounds__(768, 1) rnn_kernel(
    const float* __restrict__ sd1_b, const float* __restrict__ sd2_b,
    const float* __restrict__ g1_bi, const float* __restrict__ g1_bh,
    const float* __restrict__ g2_bi, const float* __restrict__ g2_bh,
    const float* __restrict__ g3_bi, const float* __restrict__ g3_bh,
    const float* __restrict__ out_w, const float* __restrict__ out_b,
    float* __restrict__ d_sig, float* __restrict__ d_h, int write_h)
{
    static __shared__ RnnSmem sm;
    cg::cluster_group cl = cg::this_cluster();
    const int rank = (int)cl.block_rank();
    const int b0   = (blockIdx.x / RANKS) * BPC;
    const int tid  = threadIdx.x;
    const int wid  = tid >> 5, lane = tid & 31;

    float* base = (float*)&sm;
    float* rb[RANKS];
#pragma unroll
    for (int r = 0; r < RANKS; r++) rb[r] = (float*)cl.map_shared_rank(&sm, r);
    const int OFF_TA = (int)(sm.tta - base);
    const int OFF_TB = (int)(sm.ttb - base);
    const int OFF_H  = (int)(&sm.h[0][0] - base);
    const int OFF_OP = (int)(&sm.outp[0][0] - base);
    const float* gbi[3] = { g1_bi, g2_bi, g3_bi };
    const float* gbh[3] = { g1_bh, g2_bh, g3_bh };

    for (int i = tid; i < 3 * NCOND * BPC; i += 768) (&sm.h[0][0])[i] = 0.f;
    for (int i = tid; i < NSUB * BPC; i += 768) sm.x2[256 * BPC + i] = 0.f;  // prev=0
    cl.sync();

    for (int s = 0; s < NSTEPS; s++) {
        // ---- stage A (local): finalize prev out; refill cond/phase ----
        if (s > 0 && tid < 80) {
            int b = tid & 1, oc = tid >> 1;
            float v = sm.outp[0][tid] + sm.outp[1][tid] + sm.outp[2][tid] + sm.outp[3][tid];
            v = tanhf(v + out_b[oc]);
            sm.x2[(256 + oc) * BPC + b] = v;
            if (oc >= 10 * rank && oc < 10 * rank + 10)
                d_sig[(size_t)(b0 + b) * NSTEPS * NSUB + (size_t)(s - 1) * NSUB + oc] = v;
        }
        for (int i = tid; i < 256 * BPC; i += 768) {
            int b = i & 1, c = i >> 1;
            sm.x2[c * BPC + b] = g_cond[((size_t)(b0 + b) * NBF + (s >> 2)) * NCOND + c];
        }
        for (int i = tid; i < 80 * BPC; i += 768) {
            int b = i & 1, j = i >> 1;
            sm.x2[(296 + j) * BPC + b] = (j < NSUB)
                ? g_pre[(size_t)(b0 + b) * NSTEPS * NSUB + s * NSUB + j]
                : g_pim[(size_t)(b0 + b) * NSTEPS * NSUB + s * NSUB + (j - NSUB)];
        }
        __syncthreads();

        // ---- P1: sd1 (warps 18-23, 6-way ksplit) + gh1..3 (warps 0-17) ----
        if (wid < 18) {
            int l = wid / 6, w6 = wid % 6, kh = w6 / 3;
            int pair = (w6 % 3) * 32 + lane;                 // 0..95
            int col = 256 * (pair >> 5) + RCOLS * rank + 2 * (pair & 31);
            const __half* Wp = g_gw[2 * l + 1] + col;
            const float* v = sm.h[l];
            float a00 = 0.f, a01 = 0.f, a10 = 0.f, a11 = 0.f;
            int k0 = kh * 128;
#pragma unroll 8
            for (int k = k0; k < k0 + 128; k++) {
                float2 w2 = __half22float2(*(const __half2*)(Wp + (size_t)k * 768));
                float2 xk = *(const float2*)(v + 2 * k);
                a00 = fmaf(w2.x, xk.x, a00); a01 = fmaf(w2.x, xk.y, a01);
                a10 = fmaf(w2.y, xk.x, a10); a11 = fmaf(w2.y, xk.y, a11);
            }
            sm.part[(l * 2 + kh) * 96 + pair] = make_float4(a00, a01, a10, a11);
        } else {
            int ks = wid - 18;
            const __half* Wp = g_sd1h + RCOLS * rank + 2 * lane;
            float a00 = 0.f, a01 = 0.f, a10 = 0.f, a11 = 0.f;
            int k0 = ks * 63, k1 = k0 + 63; if (k1 > 376) k1 = 376;
#pragma unroll 7
            for (int k = k0; k < k1; k++) {
                float2 w2 = __half22float2(*(const __half2*)(Wp + (size_t)k * NCOND));
                float2 xk = *(const float2*)(sm.x2 + 2 * k);
                a00 = fmaf(w2.x, xk.x, a00); a01 = fmaf(w2.x, xk.y, a01);
                a10 = fmaf(w2.y, xk.x, a10); a11 = fmaf(w2.y, xk.y, a11);
            }
            sm.part[576 + ks * 32 + lane] = make_float4(a00, a01, a10, a11);
        }
        __syncthreads();
        if (tid < 128) {                                     // gh reduce (local)
            int b = tid & 1, l64 = tid >> 1;
            int pr = l64 >> 1, comp = (l64 & 1) * 2 + b;
            const float* pf = (const float*)sm.part;
#pragma unroll
            for (int l = 0; l < 3; l++)
#pragma unroll
                for (int t = 0; t < 3; t++) {
                    int pi = t * 32 + pr;
                    float sv = pf[((l * 2 + 0) * 96 + pi) * 4 + comp]
                             + pf[((l * 2 + 1) * 96 + pi) * 4 + comp]
                             + gbh[l][256 * t + RCOLS * rank + l64];
                    sm.ghl[l][t][tid] = sv;
                }
        } else if (tid < 256) {                              // sd1 reduce + bcast
            int e = tid - 128, b = e & 1, l64 = e >> 1;
            int pr = l64 >> 1, comp = (l64 & 1) * 2 + b;
            const float* pf = (const float*)sm.part;
            float sv = 0.f;
#pragma unroll
            for (int ks = 0; ks < 6; ks++) sv += pf[(576 + ks * 32 + pr) * 4 + comp];
            float vv = tanhf(sv + sd1_b[RCOLS * rank + l64]);
            int di = OFF_TA + (RCOLS * rank + l64) * BPC + b;
#pragma unroll
            for (int r = 0; r < RANKS; r++) rb[r][di] = vv;
        }
        cl.sync();

        // ---- P2: sd2 (24-way ksplit over 32 col-pairs) ----
        {
            const __half* Wp = g_sd2h + RCOLS * rank + 2 * lane;
            float a00 = 0.f, a01 = 0.f, a10 = 0.f, a11 = 0.f;
            int k0 = wid * 11, k1 = k0 + 11; if (k1 > 256) k1 = 256;
            for (int k = k0; k < k1; k++) {
                float2 w2 = __half22float2(*(const __half2*)(Wp + (size_t)k * NCOND));
                float2 xk = *(const float2*)(sm.tta + 2 * k);
                a00 = fmaf(w2.x, xk.x, a00); a01 = fmaf(w2.x, xk.y, a01);
                a10 = fmaf(w2.y, xk.x, a10); a11 = fmaf(w2.y, xk.y, a11);
            }
            sm.part[wid * 32 + lane] = make_float4(a00, a01, a10, a11);
        }
        __syncthreads();
        if (tid < 128) {
            int b = tid & 1, l64 = tid >> 1;
            int pr = l64 >> 1, comp = (l64 & 1) * 2 + b;
            const float* pf = (const float*)sm.part;
            float sv = 0.f;
#pragma unroll
            for (int ks = 0; ks < 24; ks++) sv += pf[(ks * 32 + pr) * 4 + comp];
            float vv = tanhf(sv + sd2_b[RCOLS * rank + l64]);
            int di = OFF_TB + (RCOLS * rank + l64) * BPC + b;
#pragma unroll
            for (int r = 0; r < RANKS; r++) rb[r][di] = vv;
        }
        cl.sync();

        // ---- P3..P5: gi_l + combine h_l (+ out partials in P5) ----
#pragma unroll
        for (int l = 0; l < 3; l++) {
            const float* xv = (l == 0) ? sm.ttb : sm.h[l - 1];
            {
                int ks = wid / 3;                            // 0..7
                int pair = (wid % 3) * 32 + lane;            // 0..95
                int col = 256 * (pair >> 5) + RCOLS * rank + 2 * (pair & 31);
                const __half* Wp = g_gw[2 * l] + col;
                float a00 = 0.f, a01 = 0.f, a10 = 0.f, a11 = 0.f;
                int k0 = ks * 32;
#pragma unroll 8
                for (int k = k0; k < k0 + 32; k++) {
                    float2 w2 = __half22float2(*(const __half2*)(Wp + (size_t)k * 768));
                    float2 xk = *(const float2*)(xv + 2 * k);
                    a00 = fmaf(w2.x, xk.x, a00); a01 = fmaf(w2.x, xk.y, a01);
                    a10 = fmaf(w2.y, xk.x, a10); a11 = fmaf(w2.y, xk.y, a11);
                }
                sm.part[ks * 96 + pair] = make_float4(a00, a01, a10, a11);
            }
            __syncthreads();
            if (tid < 128) {                                 // gi reduce + combine
                int b = tid & 1, l64 = tid >> 1;
                int pr = l64 >> 1, comp = (l64 & 1) * 2 + b;
                const float* pf = (const float*)sm.part;
                float gi[3];
#pragma unroll
                for (int t = 0; t < 3; t++) {
                    float sv = gbi[l][256 * t + RCOLS * rank + l64];
#pragma unroll
                    for (int ks = 0; ks < 8; ks++) sv += pf[(ks * 96 + t * 32 + pr) * 4 + comp];
                    gi[t] = sv;
                }
                int ci = (RCOLS * rank + l64) * BPC + b;
                float rg = sigm(gi[0] + sm.ghl[l][0][tid]);
                float zg = sigm(gi[1] + sm.ghl[l][1][tid]);
                float ng = tanhf(fmaf(rg, sm.ghl[l][2][tid], gi[2]));
                float hv = fmaf(zg, sm.h[l][ci] - ng, ng);
                int di = OFF_H + l * NCOND * BPC + ci;
#pragma unroll
                for (int r = 0; r < RANKS; r++) rb[r][di] = hv;
            }
            if (l == 2) {                                    // out partials from own h3 slice
                __syncthreads();
                if (tid < 80) {
                    int b = tid & 1, oc = tid >> 1;
                    const float* Wp = out_w + oc;
                    float a = 0.f;
#pragma unroll 8
                    for (int k = 0; k < RCOLS; k++)
                        a = fmaf(Wp[(RCOLS * rank + k) * NSUB], sm.h[2][(RCOLS * rank + k) * BPC + b], a);
                    int di = OFF_OP + rank * NSUB * BPC + tid;
#pragma unroll
                    for (int r = 0; r < RANKS; r++) rb[r][di] = a;
                }
            }
            cl.sync();
        }
    }

    // final step's output
    if (tid < 80) {
        int b = tid & 1, oc = tid >> 1;
        float v = sm.outp[0][tid] + sm.outp[1][tid] + sm.outp[2][tid] + sm.outp[3][tid];
        v = tanhf(v + out_b[oc]);
        if (oc >= 10 * rank && oc < 10 * rank + 10)
            d_sig[(size_t)(b0 + b) * NSTEPS * NSUB + (size_t)(NSTEPS - 1) * NSUB + oc] = v;
    }
    if (write_h && tid < 128) {
        int b = tid & 1, l64 = tid >> 1, col = RCOLS * rank + l64;
#pragma unroll
        for (int l = 0; l < 3; l++)
            d_h[((size_t)l * BATCH + (b0 + b)) * NCOND + col] = sm.h[l][col * BPC + b];
    }
}

// ---------------- launch ----------------
extern "C" void kernel_launch(void* const* d_in, const int* in_sizes, int n_in,
                              void* d_out, int out_size) {
    (void)n_in; (void)in_sizes;
    const float* features = (const float*)d_in[0];
    const int*   period   = (const int*)  d_in[1];
    const float* rshift   = (const float*)d_in[3];
    const float* pembed   = (const float*)d_in[4];
    const float* fd1_w = (const float*)d_in[5],  *fd1_b = (const float*)d_in[6];
    const float* c1_w  = (const float*)d_in[7],  *c1_b  = (const float*)d_in[8];
    const float* c2_w  = (const float*)d_in[9],  *c2_b  = (const float*)d_in[10];
    const float* fd2_w = (const float*)d_in[11], *fd2_b = (const float*)d_in[12];
    const float* sd1_w = (const float*)d_in[13], *sd1_b = (const float*)d_in[14];
    const float* sd2_w = (const float*)d_in[15], *sd2_b = (const float*)d_in[16];
    const float* g1_wi = (const float*)d_in[17], *g1_bi = (const float*)d_in[18];
    const float* g1_wh = (const float*)d_in[19], *g1_bh = (const float*)d_in[20];
    const float* g2_wi = (const float*)d_in[21], *g2_bi = (const float*)d_in[22];
    const float* g2_wh = (const float*)d_in[23], *g2_bh = (const float*)d_in[24];
    const float* g3_wi = (const float*)d_in[25], *g3_bi = (const float*)d_in[26];
    const float* g3_wh = (const float*)d_in[27], *g3_bh = (const float*)d_in[28];
    const float* out_w = (const float*)d_in[29], *out_b = (const float*)d_in[30];

    float* d_sig = (float*)d_out;
    const int sig_elems = BATCH * NSTEPS * NSUB;
    int write_h = (out_size >= sig_elems + 3 * BATCH * NCOND) ? 1 : 0;
    float* d_h = d_sig + sig_elems;

    prep_kernel<<<64 + 768, 256>>>(period, rshift, sd1_w, sd2_w,
                                   g1_wi, g1_wh, g2_wi, g2_wh, g3_wi, g3_wh, c1_w, c2_w);
    fd1_kernel<<<BATCH * T_IN, 256>>>(features, period, pembed, fd1_w, fd1_b);
    cond2_kernel<<<BATCH * NBF, 256>>>(c1_b, c2_b, fd2_w, fd2_b);
    rnn_kernel<<<(BATCH / BPC) * RANKS, 768>>>(sd1_b, sd2_b,
                                               g1_bi, g1_bh, g2_bi, g2_bh, g3_bi, g3_bh,
                                               out_w, out_b, d_sig, d_h, write_h);
}